// round 3
// baseline (speedup 1.0000x reference)
#include <cuda_runtime.h>

#define NMAX 100000
#define EMAX 1600000
#define CIN  128

// ---------------- scratch (device globals; no allocation allowed) ----------
__device__ int   g_deg[NMAX];
__device__ float g_dinv[NMAX];
__device__ int   g_offs[NMAX + 1];
__device__ int   g_cursor[NMAX];
__device__ int   g_bsum[256];
__device__ int   g_csr_src[EMAX];
__device__ float g_csr_norm[EMAX];
__device__ __align__(16) float g_h[NMAX * 64];     // gemm output (layer3 pitch 40)
__device__ __align__(16) float g_out[NMAX * 64];   // aggregated output (pre-relu)

// ---------------- prep: degree / dinv ---------------------------------------
__global__ void k_init(int n) {
    int i = blockIdx.x * blockDim.x + threadIdx.x;
    if (i < n) g_deg[i] = 1;  // self loop
}

__global__ void k_count(const int* __restrict__ ei, int E) {
    int e = blockIdx.x * blockDim.x + threadIdx.x;
    if (e < E) {
        int d = ei[E + e];
        atomicAdd(&g_deg[d], 1);
    }
}

__global__ void k_dinv(int n) {
    int i = blockIdx.x * blockDim.x + threadIdx.x;
    if (i < n) g_dinv[i] = rsqrtf((float)g_deg[i]);
}

// ---------------- prep: exclusive scan of in-degree (deg-1) -----------------
__global__ void k_chunk_sums(int n) {
    __shared__ int s[256];
    int t = threadIdx.x;
    int base = blockIdx.x * 1024;
    int v = 0;
    #pragma unroll
    for (int j = 0; j < 4; j++) {
        int i = base + t * 4 + j;
        if (i < n) v += g_deg[i] - 1;
    }
    s[t] = v;
    __syncthreads();
    for (int off = 128; off > 0; off >>= 1) {
        if (t < off) s[t] += s[t + off];
        __syncthreads();
    }
    if (t == 0) g_bsum[blockIdx.x] = s[0];
}

__global__ void k_bscan(int nb, int n) {
    // single thread — ~98 iterations, negligible
    int acc = 0;
    for (int b = 0; b < nb; b++) {
        int v = g_bsum[b];
        g_bsum[b] = acc;
        acc += v;
    }
    g_offs[n] = acc;
}

__global__ void k_scan_final(int n) {
    __shared__ int s[256];
    int t = threadIdx.x;
    int base = blockIdx.x * 1024;
    int loc[4];
    int v = 0;
    #pragma unroll
    for (int j = 0; j < 4; j++) {
        int i = base + t * 4 + j;
        loc[j] = (i < n) ? (g_deg[i] - 1) : 0;
        v += loc[j];
    }
    s[t] = v;
    __syncthreads();
    // inclusive Hillis-Steele
    for (int off = 1; off < 256; off <<= 1) {
        int y = 0;
        if (t >= off) y = s[t - off];
        __syncthreads();
        if (t >= off) s[t] += y;
        __syncthreads();
    }
    int run = g_bsum[blockIdx.x] + s[t] - v;  // exclusive prefix for this thread
    #pragma unroll
    for (int j = 0; j < 4; j++) {
        int i = base + t * 4 + j;
        if (i < n) {
            g_offs[i] = run;
            g_cursor[i] = run;
            run += loc[j];
        }
    }
}

__global__ void k_fill_csr(const int* __restrict__ ei, int E) {
    int e = blockIdx.x * blockDim.x + threadIdx.x;
    if (e < E) {
        int s = ei[e];
        int d = ei[E + e];
        int pos = atomicAdd(&g_cursor[d], 1);
        g_csr_src[pos] = s;
        g_csr_norm[pos] = g_dinv[s] * g_dinv[d];
    }
}

// ---------------- GEMM: g_h = act(src) @ W ----------------------------------
// BM=32 rows/block, 4x4 register tile per thread, W & X tiles in smem.
// SRC_GLOBAL: read from g_out (device global) instead of pointer arg.
template <int K, int COUT, bool RELU, bool SRC_GLOBAL>
__global__ void k_gemm(const float* __restrict__ Xarg, const float* __restrict__ W,
                       int n) {
    constexpr int BM = 32;
    constexpr int NT = COUT / 4;   // threads along n
    constexpr int MT = BM / 4;     // threads along m (8)
    constexpr int NTHREADS = NT * MT;
    __shared__ float xs[BM][K];
    __shared__ float ws[K][COUT];

    const float* X = SRC_GLOBAL ? (const float*)g_out : Xarg;

    int t = threadIdx.x;
    int base = blockIdx.x * BM;

    // load X tile (coalesced, relu fused)
    constexpr int XF4 = BM * K / 4;
    for (int idx = t; idx < XF4; idx += NTHREADS) {
        int r = idx / (K / 4), kc = idx % (K / 4);
        int gr = base + r;
        float4 v = make_float4(0.f, 0.f, 0.f, 0.f);
        if (gr < n) v = *(const float4*)&X[(size_t)gr * K + kc * 4];
        if (RELU) {
            v.x = fmaxf(v.x, 0.f); v.y = fmaxf(v.y, 0.f);
            v.z = fmaxf(v.z, 0.f); v.w = fmaxf(v.w, 0.f);
        }
        *(float4*)&xs[r][kc * 4] = v;
    }
    // load W tile
    constexpr int WF4 = K * COUT / 4;
    float* wsf = &ws[0][0];
    for (int idx = t; idx < WF4; idx += NTHREADS) {
        *(float4*)&wsf[idx * 4] = *(const float4*)&W[idx * 4];
    }
    __syncthreads();

    int nidx = t % NT;
    int midx = t / NT;
    float acc[4][4] = {};

    #pragma unroll 8
    for (int k = 0; k < K; k++) {
        float4 b4 = *(float4*)&ws[k][nidx * 4];
        float a0 = xs[midx * 4 + 0][k];
        float a1 = xs[midx * 4 + 1][k];
        float a2 = xs[midx * 4 + 2][k];
        float a3 = xs[midx * 4 + 3][k];
        acc[0][0] += a0 * b4.x; acc[0][1] += a0 * b4.y; acc[0][2] += a0 * b4.z; acc[0][3] += a0 * b4.w;
        acc[1][0] += a1 * b4.x; acc[1][1] += a1 * b4.y; acc[1][2] += a1 * b4.z; acc[1][3] += a1 * b4.w;
        acc[2][0] += a2 * b4.x; acc[2][1] += a2 * b4.y; acc[2][2] += a2 * b4.z; acc[2][3] += a2 * b4.w;
        acc[3][0] += a3 * b4.x; acc[3][1] += a3 * b4.y; acc[3][2] += a3 * b4.z; acc[3][3] += a3 * b4.w;
    }

    #pragma unroll
    for (int i = 0; i < 4; i++) {
        int gr = base + midx * 4 + i;
        if (gr < n) {
            *(float4*)&g_h[(size_t)gr * COUT + nidx * 4] =
                make_float4(acc[i][0], acc[i][1], acc[i][2], acc[i][3]);
        }
    }
}

// ---------------- aggregation: out = b + dinv^2*h[i] + sum norm*h[src] ------
// one warp per node; lane owns 2 channels. Reads g_h; writes g_out or OUT arg.
template <int C, bool OUT_GLOBAL>
__global__ void k_agg(const float* __restrict__ b, float* __restrict__ OUTarg,
                      int n) {
    float* OUT = OUT_GLOBAL ? (float*)g_out : OUTarg;
    const float* H = (const float*)g_h;

    int warp = (blockIdx.x * blockDim.x + threadIdx.x) >> 5;
    int lane = threadIdx.x & 31;
    if (warp >= n) return;
    int node = warp;
    int c = lane * 2;
    bool act = (c < C);

    float di = g_dinv[node];
    float2 acc = make_float2(0.f, 0.f);
    if (act) {
        float2 hv = *(const float2*)&H[(size_t)node * C + c];
        float w = di * di;
        acc.x = b[c]     + w * hv.x;
        acc.y = b[c + 1] + w * hv.y;
    }

    int e0 = g_offs[node];
    int e1 = g_offs[node + 1];
    for (int e = e0; e < e1; e += 32) {
        int rem = e1 - e;
        int src = 0;
        float nr = 0.f;
        if (lane < rem) {
            src = g_csr_src[e + lane];
            nr  = g_csr_norm[e + lane];
        }
        int cnt = rem < 32 ? rem : 32;
        for (int j = 0; j < cnt; j++) {
            int   ss = __shfl_sync(0xffffffffu, src, j);
            float nn = __shfl_sync(0xffffffffu, nr, j);
            if (act) {
                float2 hv = *(const float2*)&H[(size_t)ss * C + c];
                acc.x += nn * hv.x;
                acc.y += nn * hv.y;
            }
        }
    }
    if (act) *(float2*)&OUT[(size_t)node * C + c] = acc;
}

// ---------------- launcher ---------------------------------------------------
extern "C" void kernel_launch(void* const* d_in, const int* in_sizes, int n_in,
                              void* d_out, int out_size) {
    const float* x  = (const float*)d_in[0];
    const int*   ei = (const int*)d_in[1];      // int32: harness converts int64
    const float* W1 = (const float*)d_in[2];
    const float* b1 = (const float*)d_in[3];
    const float* W2 = (const float*)d_in[4];
    const float* b2 = (const float*)d_in[5];
    const float* W3 = (const float*)d_in[6];
    const float* b3 = (const float*)d_in[7];
    float* out = (float*)d_out;

    int n = in_sizes[0] / CIN;
    int E = in_sizes[1] / 2;
    if (n > NMAX) n = NMAX;
    if (E > EMAX) E = EMAX;
    int nb = (n + 1023) / 1024;

    // prep
    k_init<<<(n + 255) / 256, 256>>>(n);
    k_count<<<(E + 255) / 256, 256>>>(ei, E);
    k_dinv<<<(n + 255) / 256, 256>>>(n);
    k_chunk_sums<<<nb, 256>>>(n);
    k_bscan<<<1, 1>>>(nb, n);
    k_scan_final<<<nb, 256>>>(n);
    k_fill_csr<<<(E + 255) / 256, 256>>>(ei, E);

    int gemm_grid = (n + 31) / 32;
    int agg_grid  = (n + 7) / 8;  // 8 warps/block

    // layer 1: x[128] -> 64
    k_gemm<128, 64, false, false><<<gemm_grid, 16 * 8>>>(x, W1, n);
    k_agg<64, true><<<agg_grid, 256>>>(b1, nullptr, n);
    // layer 2: relu(g_out)[64] -> 64
    k_gemm<64, 64, true, true><<<gemm_grid, 16 * 8>>>(nullptr, W2, n);
    k_agg<64, true><<<agg_grid, 256>>>(b2, nullptr, n);
    // layer 3: relu(g_out)[64] -> 40
    k_gemm<64, 40, true, true><<<gemm_grid, 10 * 8>>>(nullptr, W3, n);
    k_agg<40, false><<<agg_grid, 256>>>(b3, out, n);
}

// round 4
// speedup vs baseline: 1.2811x; 1.2811x over previous
#include <cuda_runtime.h>

#define NMAX 100000
#define EMAX 1600000
#define CIN  128

// ---------------- scratch (device globals; no allocation allowed) ----------
__device__ int   g_deg[NMAX];
__device__ int   g_offs[NMAX + 1];
__device__ int   g_cursor[NMAX];
__device__ int   g_bsum[256];
__device__ __align__(16) int2  g_csr[EMAX];        // {src, float bits of norm}
__device__ __align__(16) float g_h[NMAX * 64];     // gemm output (layer3 pitch 40)
__device__ __align__(16) float g_out[NMAX * 64];   // aggregated output (pre-relu)

// ---------------- prep: degree ------------------------------------------------
__global__ void k_init(int n) {
    int i = blockIdx.x * blockDim.x + threadIdx.x;
    if (i < n) g_deg[i] = 1;  // self loop
}

__global__ void k_count(const int* __restrict__ ei, int E) {
    int e = blockIdx.x * blockDim.x + threadIdx.x;
    if (e < E) {
        int d = ei[E + e];
        atomicAdd(&g_deg[d], 1);
    }
}

// ---------------- prep: exclusive scan of in-degree (deg-1) -----------------
__global__ void k_chunk_sums(int n) {
    __shared__ int s[256];
    int t = threadIdx.x;
    int base = blockIdx.x * 1024;
    int v = 0;
    #pragma unroll
    for (int j = 0; j < 4; j++) {
        int i = base + t * 4 + j;
        if (i < n) v += g_deg[i] - 1;
    }
    s[t] = v;
    __syncthreads();
    for (int off = 128; off > 0; off >>= 1) {
        if (t < off) s[t] += s[t + off];
        __syncthreads();
    }
    if (t == 0) g_bsum[blockIdx.x] = s[0];
}

__global__ void k_bscan(int nb, int n) {
    int acc = 0;
    for (int b = 0; b < nb; b++) {
        int v = g_bsum[b];
        g_bsum[b] = acc;
        acc += v;
    }
    g_offs[n] = acc;
}

__global__ void k_scan_final(int n) {
    __shared__ int s[256];
    int t = threadIdx.x;
    int base = blockIdx.x * 1024;
    int loc[4];
    int v = 0;
    #pragma unroll
    for (int j = 0; j < 4; j++) {
        int i = base + t * 4 + j;
        loc[j] = (i < n) ? (g_deg[i] - 1) : 0;
        v += loc[j];
    }
    s[t] = v;
    __syncthreads();
    for (int off = 1; off < 256; off <<= 1) {
        int y = 0;
        if (t >= off) y = s[t - off];
        __syncthreads();
        if (t >= off) s[t] += y;
        __syncthreads();
    }
    int run = g_bsum[blockIdx.x] + s[t] - v;
    #pragma unroll
    for (int j = 0; j < 4; j++) {
        int i = base + t * 4 + j;
        if (i < n) {
            g_offs[i] = run;
            g_cursor[i] = run;
            run += loc[j];
        }
    }
}

__global__ void k_fill_csr(const int* __restrict__ ei, int E) {
    int e = blockIdx.x * blockDim.x + threadIdx.x;
    if (e < E) {
        int s = ei[e];
        int d = ei[E + e];
        float norm = rsqrtf((float)g_deg[s]) * rsqrtf((float)g_deg[d]);
        int pos = atomicAdd(&g_cursor[d], 1);
        g_csr[pos] = make_int2(s, __float_as_int(norm));
    }
}

// ---------------- GEMM: g_h = act(src) @ W  (persistent, W resident) --------
template <int K, int COUT, bool RELU, bool SRC_GLOBAL>
__global__ void k_gemm(const float* __restrict__ Xarg, const float* __restrict__ W,
                       int n) {
    constexpr int BM = 32;
    constexpr int NT = COUT / 4;   // threads along n
    constexpr int MT = BM / 4;     // threads along m (8)
    constexpr int NTHREADS = NT * MT;
    __shared__ float ws[K][COUT];
    __shared__ float xs[BM][K];

    const float* X = SRC_GLOBAL ? (const float*)g_out : Xarg;
    int t = threadIdx.x;

    // load W once per block
    constexpr int WF4 = K * COUT / 4;
    float* wsf = &ws[0][0];
    for (int idx = t; idx < WF4; idx += NTHREADS)
        *(float4*)&wsf[idx * 4] = *(const float4*)&W[idx * 4];

    int nidx = t % NT;
    int midx = t / NT;
    int ntiles = (n + BM - 1) / BM;

    for (int tile = blockIdx.x; tile < ntiles; tile += gridDim.x) {
        int base = tile * BM;
        __syncthreads();   // protects xs reuse; also orders W before 1st compute
        constexpr int XF4 = BM * K / 4;
        for (int idx = t; idx < XF4; idx += NTHREADS) {
            int r = idx / (K / 4), kc = idx % (K / 4);
            int gr = base + r;
            float4 v = make_float4(0.f, 0.f, 0.f, 0.f);
            if (gr < n) v = *(const float4*)&X[(size_t)gr * K + kc * 4];
            if (RELU) {
                v.x = fmaxf(v.x, 0.f); v.y = fmaxf(v.y, 0.f);
                v.z = fmaxf(v.z, 0.f); v.w = fmaxf(v.w, 0.f);
            }
            *(float4*)&xs[r][kc * 4] = v;
        }
        __syncthreads();

        float acc[4][4] = {};
        #pragma unroll 8
        for (int k = 0; k < K; k++) {
            float4 b4 = *(float4*)&ws[k][nidx * 4];
            float a0 = xs[midx * 4 + 0][k];
            float a1 = xs[midx * 4 + 1][k];
            float a2 = xs[midx * 4 + 2][k];
            float a3 = xs[midx * 4 + 3][k];
            acc[0][0] += a0 * b4.x; acc[0][1] += a0 * b4.y; acc[0][2] += a0 * b4.z; acc[0][3] += a0 * b4.w;
            acc[1][0] += a1 * b4.x; acc[1][1] += a1 * b4.y; acc[1][2] += a1 * b4.z; acc[1][3] += a1 * b4.w;
            acc[2][0] += a2 * b4.x; acc[2][1] += a2 * b4.y; acc[2][2] += a2 * b4.z; acc[2][3] += a2 * b4.w;
            acc[3][0] += a3 * b4.x; acc[3][1] += a3 * b4.y; acc[3][2] += a3 * b4.z; acc[3][3] += a3 * b4.w;
        }

        #pragma unroll
        for (int i = 0; i < 4; i++) {
            int gr = base + midx * 4 + i;
            if (gr < n) {
                *(float4*)&g_h[(size_t)gr * COUT + nidx * 4] =
                    make_float4(acc[i][0], acc[i][1], acc[i][2], acc[i][3]);
            }
        }
    }
}

// ---------------- aggregation: out = b + h[i]/deg + sum norm*h[src] ---------
// one warp per node; lane owns 2 channels; edge record broadcast-loaded.
template <int C, bool OUT_GLOBAL>
__global__ void k_agg(const float* __restrict__ b, float* __restrict__ OUTarg,
                      int n) {
    float* OUT = OUT_GLOBAL ? (float*)g_out : OUTarg;
    const float* H = (const float*)g_h;

    int warp = (blockIdx.x * blockDim.x + threadIdx.x) >> 5;
    int lane = threadIdx.x & 31;
    if (warp >= n) return;
    int node = warp;
    int c = lane * 2;
    bool act = (c < C);

    float2 acc = make_float2(0.f, 0.f);
    if (act) {
        float2 hv = *(const float2*)&H[(size_t)node * C + c];
        float w = 1.0f / (float)g_deg[node];   // dinv^2
        acc.x = b[c]     + w * hv.x;
        acc.y = b[c + 1] + w * hv.y;
    }

    int e0 = g_offs[node];
    int e1 = g_offs[node + 1];
    int e = e0;
    // unrolled by 4 for MLP; edge record is same-address (broadcast) load
    for (; e + 4 <= e1; e += 4) {
        int2 r0 = g_csr[e];
        int2 r1 = g_csr[e + 1];
        int2 r2 = g_csr[e + 2];
        int2 r3 = g_csr[e + 3];
        if (act) {
            float2 h0 = *(const float2*)&H[(size_t)r0.x * C + c];
            float2 h1 = *(const float2*)&H[(size_t)r1.x * C + c];
            float2 h2 = *(const float2*)&H[(size_t)r2.x * C + c];
            float2 h3 = *(const float2*)&H[(size_t)r3.x * C + c];
            float n0 = __int_as_float(r0.y), n1 = __int_as_float(r1.y);
            float n2 = __int_as_float(r2.y), n3 = __int_as_float(r3.y);
            acc.x += n0 * h0.x; acc.y += n0 * h0.y;
            acc.x += n1 * h1.x; acc.y += n1 * h1.y;
            acc.x += n2 * h2.x; acc.y += n2 * h2.y;
            acc.x += n3 * h3.x; acc.y += n3 * h3.y;
        }
    }
    for (; e < e1; e++) {
        int2 r = g_csr[e];
        if (act) {
            float2 hv = *(const float2*)&H[(size_t)r.x * C + c];
            float nn = __int_as_float(r.y);
            acc.x += nn * hv.x; acc.y += nn * hv.y;
        }
    }
    if (act) *(float2*)&OUT[(size_t)node * C + c] = acc;
}

// ---------------- launcher ---------------------------------------------------
extern "C" void kernel_launch(void* const* d_in, const int* in_sizes, int n_in,
                              void* d_out, int out_size) {
    const float* x  = (const float*)d_in[0];
    const int*   ei = (const int*)d_in[1];      // int32 (harness converts int64)
    const float* W1 = (const float*)d_in[2];
    const float* b1 = (const float*)d_in[3];
    const float* W2 = (const float*)d_in[4];
    const float* b2 = (const float*)d_in[5];
    const float* W3 = (const float*)d_in[6];
    const float* b3 = (const float*)d_in[7];
    float* out = (float*)d_out;

    int n = in_sizes[0] / CIN;
    int E = in_sizes[1] / 2;
    if (n > NMAX) n = NMAX;
    if (E > EMAX) E = EMAX;
    int nb = (n + 1023) / 1024;

    // prep
    k_init<<<(n + 255) / 256, 256>>>(n);
    k_count<<<(E + 255) / 256, 256>>>(ei, E);
    k_chunk_sums<<<nb, 256>>>(n);
    k_bscan<<<1, 1>>>(nb, n);
    k_scan_final<<<nb, 256>>>(n);
    k_fill_csr<<<(E + 255) / 256, 256>>>(ei, E);

    int agg_grid = (n + 7) / 8;  // 8 warps/block

    // layer 1: x[128] -> 64  (smem 48KB -> ~4 blocks/SM)
    k_gemm<128, 64, false, false><<<592, 16 * 8>>>(x, W1, n);
    k_agg<64, true><<<agg_grid, 256>>>(b1, nullptr, n);
    // layer 2: relu(g_out)[64] -> 64
    k_gemm<64, 64, true, true><<<1184, 16 * 8>>>(nullptr, W2, n);
    k_agg<64, true><<<agg_grid, 256>>>(b2, nullptr, n);
    // layer 3: relu(g_out)[64] -> 40
    k_gemm<64, 40, true, true><<<1184, 10 * 8>>>(nullptr, W3, n);
    k_agg<40, false><<<agg_grid, 256>>>(b3, out, n);
}

// round 5
// speedup vs baseline: 1.4716x; 1.1487x over previous
#include <cuda_runtime.h>
#include <cuda_fp16.h>

#define NMAX 100000
#define EMAX 1600000
#define CIN  128

// ---------------- scratch (device globals; no allocation allowed) ----------
__device__ int   g_deg[NMAX];
__device__ int   g_offs[NMAX + 1];
__device__ int   g_cursor[NMAX];
__device__ int   g_bsum[256];
__device__ __align__(16) int2   g_csr[EMAX];       // {src, float bits of norm}
__device__ __align__(16) __half g_h[NMAX * 64];    // gemm output, fp16 (layer3 pitch 40)
__device__ __align__(16) float  g_out[NMAX * 64];  // aggregated output (pre-relu), fp32

// ---------------- prep: degree ------------------------------------------------
__global__ void k_init(int n) {
    int i = blockIdx.x * blockDim.x + threadIdx.x;
    if (i < n) g_deg[i] = 1;  // self loop
}

__global__ void k_count(const int* __restrict__ ei, int E) {
    int e = blockIdx.x * blockDim.x + threadIdx.x;
    if (e < E) {
        int d = ei[E + e];
        atomicAdd(&g_deg[d], 1);
    }
}

// ---------------- prep: exclusive scan of in-degree (deg-1) -----------------
__global__ void k_chunk_sums(int n) {
    __shared__ int s[256];
    int t = threadIdx.x;
    int base = blockIdx.x * 1024;
    int v = 0;
    #pragma unroll
    for (int j = 0; j < 4; j++) {
        int i = base + t * 4 + j;
        if (i < n) v += g_deg[i] - 1;
    }
    s[t] = v;
    __syncthreads();
    for (int off = 128; off > 0; off >>= 1) {
        if (t < off) s[t] += s[t + off];
        __syncthreads();
    }
    if (t == 0) g_bsum[blockIdx.x] = s[0];
}

__global__ void k_bscan(int nb, int n) {
    int acc = 0;
    for (int b = 0; b < nb; b++) {
        int v = g_bsum[b];
        g_bsum[b] = acc;
        acc += v;
    }
    g_offs[n] = acc;
}

__global__ void k_scan_final(int n) {
    __shared__ int s[256];
    int t = threadIdx.x;
    int base = blockIdx.x * 1024;
    int loc[4];
    int v = 0;
    #pragma unroll
    for (int j = 0; j < 4; j++) {
        int i = base + t * 4 + j;
        loc[j] = (i < n) ? (g_deg[i] - 1) : 0;
        v += loc[j];
    }
    s[t] = v;
    __syncthreads();
    for (int off = 1; off < 256; off <<= 1) {
        int y = 0;
        if (t >= off) y = s[t - off];
        __syncthreads();
        if (t >= off) s[t] += y;
        __syncthreads();
    }
    int run = g_bsum[blockIdx.x] + s[t] - v;
    #pragma unroll
    for (int j = 0; j < 4; j++) {
        int i = base + t * 4 + j;
        if (i < n) {
            g_offs[i] = run;
            g_cursor[i] = run;
            run += loc[j];
        }
    }
}

__global__ void k_fill_csr(const int* __restrict__ ei, int E) {
    int e = blockIdx.x * blockDim.x + threadIdx.x;
    if (e < E) {
        int s = ei[e];
        int d = ei[E + e];
        float norm = rsqrtf((float)g_deg[s]) * rsqrtf((float)g_deg[d]);
        int pos = atomicAdd(&g_cursor[d], 1);
        g_csr[pos] = make_int2(s, __float_as_int(norm));
    }
}

// ---------------- GEMM: g_h(fp16) = act(src) @ W  (persistent, W resident) --
template <int K, int COUT, bool RELU, bool SRC_GLOBAL>
__global__ void k_gemm(const float* __restrict__ Xarg, const float* __restrict__ W,
                       int n) {
    constexpr int BM = 32;
    constexpr int NT = COUT / 4;   // threads along n
    constexpr int MT = BM / 4;     // threads along m (8)
    constexpr int NTHREADS = NT * MT;
    __shared__ float ws[K][COUT];
    __shared__ float xs[BM][K];

    const float* X = SRC_GLOBAL ? (const float*)g_out : Xarg;
    int t = threadIdx.x;

    // load W once per block
    constexpr int WF4 = K * COUT / 4;
    float* wsf = &ws[0][0];
    for (int idx = t; idx < WF4; idx += NTHREADS)
        *(float4*)&wsf[idx * 4] = *(const float4*)&W[idx * 4];

    int nidx = t % NT;
    int midx = t / NT;
    int ntiles = (n + BM - 1) / BM;

    for (int tile = blockIdx.x; tile < ntiles; tile += gridDim.x) {
        int base = tile * BM;
        __syncthreads();   // protects xs reuse; also orders W before 1st compute
        constexpr int XF4 = BM * K / 4;
        for (int idx = t; idx < XF4; idx += NTHREADS) {
            int r = idx / (K / 4), kc = idx % (K / 4);
            int gr = base + r;
            float4 v = make_float4(0.f, 0.f, 0.f, 0.f);
            if (gr < n) v = *(const float4*)&X[(size_t)gr * K + kc * 4];
            if (RELU) {
                v.x = fmaxf(v.x, 0.f); v.y = fmaxf(v.y, 0.f);
                v.z = fmaxf(v.z, 0.f); v.w = fmaxf(v.w, 0.f);
            }
            *(float4*)&xs[r][kc * 4] = v;
        }
        __syncthreads();

        float acc[4][4] = {};
        #pragma unroll 8
        for (int k = 0; k < K; k++) {
            float4 b4 = *(float4*)&ws[k][nidx * 4];
            float a0 = xs[midx * 4 + 0][k];
            float a1 = xs[midx * 4 + 1][k];
            float a2 = xs[midx * 4 + 2][k];
            float a3 = xs[midx * 4 + 3][k];
            acc[0][0] += a0 * b4.x; acc[0][1] += a0 * b4.y; acc[0][2] += a0 * b4.z; acc[0][3] += a0 * b4.w;
            acc[1][0] += a1 * b4.x; acc[1][1] += a1 * b4.y; acc[1][2] += a1 * b4.z; acc[1][3] += a1 * b4.w;
            acc[2][0] += a2 * b4.x; acc[2][1] += a2 * b4.y; acc[2][2] += a2 * b4.z; acc[2][3] += a2 * b4.w;
            acc[3][0] += a3 * b4.x; acc[3][1] += a3 * b4.y; acc[3][2] += a3 * b4.z; acc[3][3] += a3 * b4.w;
        }

        #pragma unroll
        for (int i = 0; i < 4; i++) {
            int gr = base + midx * 4 + i;
            if (gr < n) {
                __half2 p0 = __floats2half2_rn(acc[i][0], acc[i][1]);
                __half2 p1 = __floats2half2_rn(acc[i][2], acc[i][3]);
                uint2 u = make_uint2(*(unsigned*)&p0, *(unsigned*)&p1);
                *(uint2*)&g_h[(size_t)gr * COUT + nidx * 4] = u;
            }
        }
    }
}

// ---------------- aggregation: out = b + h[i]/deg + sum norm*h[src] ---------
// one warp per node; lane owns 2 channels; edge record broadcast-loaded;
// h gathered as fp16, accumulated fp32.
template <int C, bool OUT_GLOBAL>
__global__ void k_agg(const float* __restrict__ b, float* __restrict__ OUTarg,
                      int n) {
    float* OUT = OUT_GLOBAL ? (float*)g_out : OUTarg;
    const __half* H = (const __half*)g_h;

    int warp = (blockIdx.x * blockDim.x + threadIdx.x) >> 5;
    int lane = threadIdx.x & 31;
    if (warp >= n) return;
    int node = warp;
    int c = lane * 2;
    bool act = (c < C);

    float2 acc = make_float2(0.f, 0.f);
    if (act) {
        float2 hv = __half22float2(*(const __half2*)&H[(size_t)node * C + c]);
        float w = 1.0f / (float)g_deg[node];   // dinv^2
        acc.x = b[c]     + w * hv.x;
        acc.y = b[c + 1] + w * hv.y;
    }

    int e0 = g_offs[node];
    int e1 = g_offs[node + 1];
    int e = e0;
    for (; e + 4 <= e1; e += 4) {
        int2 r0 = g_csr[e];
        int2 r1 = g_csr[e + 1];
        int2 r2 = g_csr[e + 2];
        int2 r3 = g_csr[e + 3];
        if (act) {
            float2 h0 = __half22float2(*(const __half2*)&H[(size_t)r0.x * C + c]);
            float2 h1 = __half22float2(*(const __half2*)&H[(size_t)r1.x * C + c]);
            float2 h2 = __half22float2(*(const __half2*)&H[(size_t)r2.x * C + c]);
            float2 h3 = __half22float2(*(const __half2*)&H[(size_t)r3.x * C + c]);
            float n0 = __int_as_float(r0.y), n1 = __int_as_float(r1.y);
            float n2 = __int_as_float(r2.y), n3 = __int_as_float(r3.y);
            acc.x += n0 * h0.x; acc.y += n0 * h0.y;
            acc.x += n1 * h1.x; acc.y += n1 * h1.y;
            acc.x += n2 * h2.x; acc.y += n2 * h2.y;
            acc.x += n3 * h3.x; acc.y += n3 * h3.y;
        }
    }
    for (; e < e1; e++) {
        int2 r = g_csr[e];
        if (act) {
            float2 hv = __half22float2(*(const __half2*)&H[(size_t)r.x * C + c]);
            float nn = __int_as_float(r.y);
            acc.x += nn * hv.x; acc.y += nn * hv.y;
        }
    }
    if (act) *(float2*)&OUT[(size_t)node * C + c] = acc;
}

// ---------------- launcher ---------------------------------------------------
extern "C" void kernel_launch(void* const* d_in, const int* in_sizes, int n_in,
                              void* d_out, int out_size) {
    const float* x  = (const float*)d_in[0];
    const int*   ei = (const int*)d_in[1];      // int32 (harness converts int64)
    const float* W1 = (const float*)d_in[2];
    const float* b1 = (const float*)d_in[3];
    const float* W2 = (const float*)d_in[4];
    const float* b2 = (const float*)d_in[5];
    const float* W3 = (const float*)d_in[6];
    const float* b3 = (const float*)d_in[7];
    float* out = (float*)d_out;

    int n = in_sizes[0] / CIN;
    int E = in_sizes[1] / 2;
    if (n > NMAX) n = NMAX;
    if (E > EMAX) E = EMAX;
    int nb = (n + 1023) / 1024;

    // side stream + events for prep || GEMM1 overlap (capturable fork/join)
    static cudaStream_t s2 = nullptr;
    static cudaEvent_t evFork = nullptr, evJoin = nullptr;
    if (!s2) {
        cudaStreamCreate(&s2);
        cudaEventCreateWithFlags(&evFork, cudaEventDisableTiming);
        cudaEventCreateWithFlags(&evJoin, cudaEventDisableTiming);
    }

    // fork: prep chain on s2, GEMM1 on main stream
    cudaEventRecord(evFork, 0);
    cudaStreamWaitEvent(s2, evFork, 0);

    k_init<<<(n + 255) / 256, 256, 0, s2>>>(n);
    k_count<<<(E + 255) / 256, 256, 0, s2>>>(ei, E);
    k_chunk_sums<<<nb, 256, 0, s2>>>(n);
    k_bscan<<<1, 1, 0, s2>>>(nb, n);
    k_scan_final<<<nb, 256, 0, s2>>>(n);
    k_fill_csr<<<(E + 255) / 256, 256, 0, s2>>>(ei, E);
    cudaEventRecord(evJoin, s2);

    // layer 1 GEMM: x[128] -> 64 (independent of CSR prep)
    k_gemm<128, 64, false, false><<<592, 16 * 8>>>(x, W1, n);

    // join: aggregation needs both GEMM1 and CSR
    cudaStreamWaitEvent(0, evJoin, 0);

    int agg_grid = (n + 7) / 8;  // 8 warps/block
    k_agg<64, true><<<agg_grid, 256>>>(b1, nullptr, n);
    // layer 2: relu(g_out)[64] -> 64
    k_gemm<64, 64, true, true><<<1184, 16 * 8>>>(nullptr, W2, n);
    k_agg<64, true><<<agg_grid, 256>>>(b2, nullptr, n);
    // layer 3: relu(g_out)[64] -> 40
    k_gemm<64, 40, true, true><<<1184, 10 * 8>>>(nullptr, W3, n);
    k_agg<40, false><<<agg_grid, 256>>>(b3, out, n);
}